// round 1
// baseline (speedup 1.0000x reference)
#include <cuda_runtime.h>
#include <cuda_bf16.h>
#include <cstdint>

// Problem constants (fixed by the reference)
constexpr int N_NODES = 50000;
constexpr int N_EDGES = 800000;
constexpr int IN_F    = 256;
constexpr int OUT_F   = 64;

// Scratch: projected+source-scaled node features  hws[i] = (h[i] @ W) * norm[i]
// 50000*64 floats = 12.8 MB -> lives in L2 during the scatter phase.
__device__ float g_hws[(size_t)N_NODES * OUT_F];

// ---------------------------------------------------------------------------
// Kernel 1: hws = (h @ W) * norm[row]
// 64x64 output tile per 256-thread block, 4x4 register microtile, K-chunk 64.
// ---------------------------------------------------------------------------
__global__ __launch_bounds__(256) void gemm_norm_kernel(
    const float* __restrict__ h,
    const float* __restrict__ W,
    const float* __restrict__ norm)
{
    __shared__ float shA[64][68];  // [row][k], pad 68 -> 16B-aligned float4 rows,
                                   // conflict-free column reads
    __shared__ float shB[64][64];  // [k][out]

    const int tid = threadIdx.x;
    const int ty = tid >> 4;        // 0..15
    const int tx = tid & 15;        // 0..15
    const int r0 = ty * 4;          // thread's 4 rows within tile
    const int c0 = tx * 4;          // thread's 4 cols
    const int block_row = blockIdx.x * 64;

    float acc[4][4] = {};

    for (int kc = 0; kc < IN_F; kc += 64) {
        // --- stage tiles: each thread moves 4 float4 of A and 4 float4 of B ---
#pragma unroll
        for (int j = 0; j < 4; ++j) {
            const int i   = tid + 256 * j;     // 0..1023
            const int row = i >> 4;            // 0..63
            const int kk  = (i & 15) * 4;      // 0..60 step 4

            float4 va = make_float4(0.f, 0.f, 0.f, 0.f);
            const int grow = block_row + row;
            if (grow < N_NODES)
                va = *reinterpret_cast<const float4*>(h + (size_t)grow * IN_F + kc + kk);
            *reinterpret_cast<float4*>(&shA[row][kk]) = va;

            const int k  = row;                // reuse decomposition: k chunk row
            const int cc = kk;                 // 0..60 step 4
            float4 vb = *reinterpret_cast<const float4*>(W + (size_t)(kc + k) * OUT_F + cc);
            *reinterpret_cast<float4*>(&shB[k][cc]) = vb;
        }
        __syncthreads();

        // --- compute ---
#pragma unroll
        for (int k = 0; k < 64; ++k) {
            const float4 b = *reinterpret_cast<const float4*>(&shB[k][c0]);
            const float a0 = shA[r0 + 0][k];
            const float a1 = shA[r0 + 1][k];
            const float a2 = shA[r0 + 2][k];
            const float a3 = shA[r0 + 3][k];
            acc[0][0] += a0 * b.x; acc[0][1] += a0 * b.y; acc[0][2] += a0 * b.z; acc[0][3] += a0 * b.w;
            acc[1][0] += a1 * b.x; acc[1][1] += a1 * b.y; acc[1][2] += a1 * b.z; acc[1][3] += a1 * b.w;
            acc[2][0] += a2 * b.x; acc[2][1] += a2 * b.y; acc[2][2] += a2 * b.z; acc[2][3] += a2 * b.w;
            acc[3][0] += a3 * b.x; acc[3][1] += a3 * b.y; acc[3][2] += a3 * b.z; acc[3][3] += a3 * b.w;
        }
        __syncthreads();
    }

    // --- epilogue: scale by norm[row] (folds the per-edge src scaling) ---
#pragma unroll
    for (int i2 = 0; i2 < 4; ++i2) {
        const int grow = block_row + r0 + i2;
        if (grow < N_NODES) {
            const float s = norm[grow];
            float4 o;
            o.x = acc[i2][0] * s;
            o.y = acc[i2][1] * s;
            o.z = acc[i2][2] * s;
            o.w = acc[i2][3] * s;
            *reinterpret_cast<float4*>(g_hws + (size_t)grow * OUT_F + c0) = o;
        }
    }
}

// ---------------------------------------------------------------------------
// Kernel 2: scatter-add  out[dst[e]] += hws[src[e]]
// 16 threads per edge, float4 gather + red.global.add.v4.f32 scatter.
// ---------------------------------------------------------------------------
__global__ __launch_bounds__(256) void scatter_kernel(
    const int* __restrict__ src,
    const int* __restrict__ dst,
    float* __restrict__ out)
{
    const int g = blockIdx.x * 256 + threadIdx.x;
    const int e = g >> 4;
    if (e >= N_EDGES) return;
    const int part = (g & 15) * 4;

    const int s = __ldg(src + e);
    const int d = __ldg(dst + e);

    const float4 v = *reinterpret_cast<const float4*>(g_hws + (size_t)s * OUT_F + part);
    float* p = out + (size_t)d * OUT_F + part;

    asm volatile("red.global.add.v4.f32 [%0], {%1, %2, %3, %4};"
                 :: "l"(p), "f"(v.x), "f"(v.y), "f"(v.z), "f"(v.w)
                 : "memory");
}

// ---------------------------------------------------------------------------
// Kernel 3: out = relu(out * norm[row] + bias[col])
// One float4 per thread.
// ---------------------------------------------------------------------------
__global__ __launch_bounds__(256) void finalize_kernel(
    float* __restrict__ out,
    const float* __restrict__ norm,
    const float* __restrict__ bias)
{
    const int i = blockIdx.x * 256 + threadIdx.x;   // float4 index
    constexpr int TOTAL4 = N_NODES * OUT_F / 4;     // 800000
    if (i >= TOTAL4) return;

    const int row = i >> 4;                          // 16 float4 per row
    const float s = __ldg(norm + row);
    const float4 b = reinterpret_cast<const float4*>(bias)[i & 15];

    float4 v = reinterpret_cast<float4*>(out)[i];
    v.x = fmaxf(fmaf(v.x, s, b.x), 0.f);
    v.y = fmaxf(fmaf(v.y, s, b.y), 0.f);
    v.z = fmaxf(fmaf(v.z, s, b.z), 0.f);
    v.w = fmaxf(fmaf(v.w, s, b.w), 0.f);
    reinterpret_cast<float4*>(out)[i] = v;
}

// ---------------------------------------------------------------------------
// Launch
// Inputs (metadata order = setup_inputs dict order):
//   0: h      [50000, 256] f32
//   1: norm   [50000]      f32
//   2: src    [800000]     i32
//   3: dst    [800000]     i32
//   4: weight [256, 64]    f32
//   5: bias   [64]         f32
// Output: [50000, 64] f32
// ---------------------------------------------------------------------------
extern "C" void kernel_launch(void* const* d_in, const int* in_sizes, int n_in,
                              void* d_out, int out_size)
{
    const float* h    = (const float*)d_in[0];
    const float* norm = (const float*)d_in[1];
    const int*   src  = (const int*)d_in[2];
    const int*   dst  = (const int*)d_in[3];
    const float* W    = (const float*)d_in[4];
    const float* bias = (const float*)d_in[5];
    float* out = (float*)d_out;

    // zero the accumulation buffer (atomics target d_out directly)
    cudaMemsetAsync(d_out, 0, (size_t)out_size * sizeof(float));

    // 1) hws = (h @ W) * norm
    gemm_norm_kernel<<<(N_NODES + 63) / 64, 256>>>(h, W, norm);

    // 2) out[dst] += hws[src]
    const int scatter_threads = N_EDGES * 16;
    scatter_kernel<<<(scatter_threads + 255) / 256, 256>>>(src, dst, out);

    // 3) out = relu(out * norm + bias)
    constexpr int TOTAL4 = N_NODES * OUT_F / 4;
    finalize_kernel<<<(TOTAL4 + 255) / 256, 256>>>(out, norm, bias);
}

// round 2
// speedup vs baseline: 1.3295x; 1.3295x over previous
#include <cuda_runtime.h>
#include <cuda_bf16.h>
#include <cstdint>

// Problem constants (fixed by the reference)
constexpr int N_NODES = 50000;
constexpr int N_EDGES = 800000;
constexpr int IN_F    = 256;
constexpr int OUT_F   = 64;

// Scratch: projected+source-scaled node features  hws[i] = (h[i] @ W) * norm[i]
// 50000*64 floats = 12.8 MB -> L2-resident during the scatter phase.
__device__ float g_hws[(size_t)N_NODES * OUT_F];

// ---------------------------------------------------------------------------
// tf32 helpers
// ---------------------------------------------------------------------------
__device__ __forceinline__ uint32_t f2tf32(float x) {
    uint32_t r;
    asm("cvt.rna.tf32.f32 %0, %1;" : "=r"(r) : "f"(x));
    return r;
}

__device__ __forceinline__ void mma_tf32(float c[4], const uint32_t a[4],
                                         uint32_t b0, uint32_t b1) {
    asm volatile(
        "mma.sync.aligned.m16n8k8.row.col.f32.tf32.tf32.f32 "
        "{%0,%1,%2,%3}, {%4,%5,%6,%7}, {%8,%9}, {%0,%1,%2,%3};"
        : "+f"(c[0]), "+f"(c[1]), "+f"(c[2]), "+f"(c[3])
        : "r"(a[0]), "r"(a[1]), "r"(a[2]), "r"(a[3]), "r"(b0), "r"(b1));
}

// ---------------------------------------------------------------------------
// Kernel 1: hws = (h @ W) * norm[row]   -- tf32 tensor-core GEMM
// Block tile 128x64, 8 warps, each warp m16 x n64, K chunk 32.
// ---------------------------------------------------------------------------
constexpr int BM = 128;   // rows per block
constexpr int KC = 32;    // K chunk
constexpr int AS = 36;    // shA row stride (floats): 4*row+col conflict-free
constexpr int BS = 72;    // shB row stride (floats): 8*k+n   conflict-free

__global__ __launch_bounds__(256) void gemm_tc_kernel(
    const float* __restrict__ h,
    const float* __restrict__ W,
    const float* __restrict__ norm)
{
    __shared__ uint32_t shA[BM * AS];
    __shared__ uint32_t shB[KC * BS];

    const int tid  = threadIdx.x;
    const int warp = tid >> 5;
    const int lane = tid & 31;
    const int block_row = blockIdx.x * BM;
    const int wr = warp * 16;                 // warp's row base within tile
    const int grp = lane >> 2;                // 0..7
    const int tig = lane & 3;                 // 0..3

    float acc[8][4] = {};                     // 8 n8-tiles x 4 accum regs

    for (int kc = 0; kc < IN_F; kc += KC) {
        // --- stage A: 128x32 floats, tf32-converted ---
#pragma unroll
        for (int j = 0; j < 4; ++j) {
            const int linear = tid + 256 * j;       // 0..1023 float4 slots
            const int row = linear >> 3;            // 0..127
            const int kk  = (linear & 7) * 4;       // 0..28
            const int grow = block_row + row;
            float4 v = make_float4(0.f, 0.f, 0.f, 0.f);
            if (grow < N_NODES)
                v = *reinterpret_cast<const float4*>(h + (size_t)grow * IN_F + kc + kk);
            uint32_t* p = &shA[row * AS + kk];
            p[0] = f2tf32(v.x); p[1] = f2tf32(v.y);
            p[2] = f2tf32(v.z); p[3] = f2tf32(v.w);
        }
        // --- stage B: 32x64 floats, tf32-converted ---
#pragma unroll
        for (int j = 0; j < 2; ++j) {
            const int linear = tid + 256 * j;       // 0..511 float4 slots
            const int k  = linear >> 4;             // 0..31
            const int cc = (linear & 15) * 4;       // 0..60
            const float4 v = *reinterpret_cast<const float4*>(
                W + (size_t)(kc + k) * OUT_F + cc);
            uint32_t* p = &shB[k * BS + cc];
            p[0] = f2tf32(v.x); p[1] = f2tf32(v.y);
            p[2] = f2tf32(v.z); p[3] = f2tf32(v.w);
        }
        __syncthreads();

        // --- compute: 4 k8 steps x 8 n-tiles ---
#pragma unroll
        for (int k8 = 0; k8 < 4; ++k8) {
            const int k0 = k8 * 8;
            uint32_t a[4];
            const int ar = wr + grp;
            const int ac = k0 + tig;
            a[0] = shA[ar * AS + ac];
            a[1] = shA[(ar + 8) * AS + ac];
            a[2] = shA[ar * AS + ac + 4];
            a[3] = shA[(ar + 8) * AS + ac + 4];
#pragma unroll
            for (int nt = 0; nt < 8; ++nt) {
                const int bk = k0 + tig;
                const int bn = nt * 8 + grp;
                const uint32_t b0 = shB[bk * BS + bn];
                const uint32_t b1 = shB[(bk + 4) * BS + bn];
                mma_tf32(acc[nt], a, b0, b1);
            }
        }
        __syncthreads();
    }

    // --- epilogue: scale by norm[row], store float2 pairs ---
    const int r0 = block_row + wr + grp;
    const int r1 = r0 + 8;
    const float s0 = (r0 < N_NODES) ? norm[r0] : 0.f;
    const float s1 = (r1 < N_NODES) ? norm[r1] : 0.f;
#pragma unroll
    for (int nt = 0; nt < 8; ++nt) {
        const int col = nt * 8 + tig * 2;
        if (r0 < N_NODES) {
            float2 v; v.x = acc[nt][0] * s0; v.y = acc[nt][1] * s0;
            *reinterpret_cast<float2*>(g_hws + (size_t)r0 * OUT_F + col) = v;
        }
        if (r1 < N_NODES) {
            float2 v; v.x = acc[nt][2] * s1; v.y = acc[nt][3] * s1;
            *reinterpret_cast<float2*>(g_hws + (size_t)r1 * OUT_F + col) = v;
        }
    }
}

// ---------------------------------------------------------------------------
// Kernel 2: scatter-add  out[dst[e]] += hws[src[e]]
// 16 threads per edge, float4 gather + red.global.add.v4.f32 scatter.
// ---------------------------------------------------------------------------
__global__ __launch_bounds__(256) void scatter_kernel(
    const int* __restrict__ src,
    const int* __restrict__ dst,
    float* __restrict__ out)
{
    const int g = blockIdx.x * 256 + threadIdx.x;
    const int e = g >> 4;
    if (e >= N_EDGES) return;
    const int part = (g & 15) * 4;

    const int s = __ldg(src + e);
    const int d = __ldg(dst + e);

    const float4 v = *reinterpret_cast<const float4*>(g_hws + (size_t)s * OUT_F + part);
    float* p = out + (size_t)d * OUT_F + part;

    asm volatile("red.global.add.v4.f32 [%0], {%1, %2, %3, %4};"
                 :: "l"(p), "f"(v.x), "f"(v.y), "f"(v.z), "f"(v.w)
                 : "memory");
}

// ---------------------------------------------------------------------------
// Kernel 3: out = relu(out * norm[row] + bias[col])
// ---------------------------------------------------------------------------
__global__ __launch_bounds__(256) void finalize_kernel(
    float* __restrict__ out,
    const float* __restrict__ norm,
    const float* __restrict__ bias)
{
    const int i = blockIdx.x * 256 + threadIdx.x;   // float4 index
    constexpr int TOTAL4 = N_NODES * OUT_F / 4;     // 800000
    if (i >= TOTAL4) return;

    const int row = i >> 4;                          // 16 float4 per row
    const float s = __ldg(norm + row);
    const float4 b = reinterpret_cast<const float4*>(bias)[i & 15];

    float4 v = reinterpret_cast<float4*>(out)[i];
    v.x = fmaxf(fmaf(v.x, s, b.x), 0.f);
    v.y = fmaxf(fmaf(v.y, s, b.y), 0.f);
    v.z = fmaxf(fmaf(v.z, s, b.z), 0.f);
    v.w = fmaxf(fmaf(v.w, s, b.w), 0.f);
    reinterpret_cast<float4*>(out)[i] = v;
}

// ---------------------------------------------------------------------------
// Launch
// Inputs: 0:h [50000,256] f32  1:norm [50000] f32  2:src [800000] i32
//         3:dst [800000] i32   4:weight [256,64] f32  5:bias [64] f32
// Output: [50000, 64] f32
// ---------------------------------------------------------------------------
extern "C" void kernel_launch(void* const* d_in, const int* in_sizes, int n_in,
                              void* d_out, int out_size)
{
    const float* h    = (const float*)d_in[0];
    const float* norm = (const float*)d_in[1];
    const int*   src  = (const int*)d_in[2];
    const int*   dst  = (const int*)d_in[3];
    const float* W    = (const float*)d_in[4];
    const float* bias = (const float*)d_in[5];
    float* out = (float*)d_out;

    // zero the accumulation buffer (atomics target d_out directly)
    cudaMemsetAsync(d_out, 0, (size_t)out_size * sizeof(float));

    // 1) hws = (h @ W) * norm   (tf32 tensor cores)
    gemm_tc_kernel<<<(N_NODES + BM - 1) / BM, 256>>>(h, W, norm);

    // 2) out[dst] += hws[src]
    const int scatter_threads = N_EDGES * 16;
    scatter_kernel<<<(scatter_threads + 255) / 256, 256>>>(src, dst, out);

    // 3) out = relu(out * norm + bias)
    constexpr int TOTAL4 = N_NODES * OUT_F / 4;
    finalize_kernel<<<(TOTAL4 + 255) / 256, 256>>>(out, norm, bias);
}

// round 3
// speedup vs baseline: 1.4322x; 1.0773x over previous
#include <cuda_runtime.h>
#include <cuda_bf16.h>
#include <cstdint>

// Problem constants (fixed by the reference)
constexpr int N_NODES = 50000;
constexpr int N_EDGES = 800000;
constexpr int IN_F    = 256;
constexpr int OUT_F   = 64;

constexpr int NB_NODES = (N_NODES + 255) / 256;   // 196 scan blocks

// Scratch (device globals: no allocation allowed in kernel_launch)
__device__ float g_hws[(size_t)N_NODES * OUT_F];  // (h@W)*norm  : 12.8 MB, L2-resident
__device__ int   g_esrc[N_EDGES];                 // src ids grouped by dst bucket
__device__ int   g_deg[N_NODES];                  // in-degree per node
__device__ int   g_off[N_NODES];                  // CSR offsets (exclusive scan of deg)
__device__ int   g_cursor[N_NODES];               // fill cursors
__device__ int   g_part[256];                     // scan block partials

// ---------------------------------------------------------------------------
// tf32 helpers
// ---------------------------------------------------------------------------
__device__ __forceinline__ uint32_t f2tf32(float x) {
    uint32_t r;
    asm("cvt.rna.tf32.f32 %0, %1;" : "=r"(r) : "f"(x));
    return r;
}

__device__ __forceinline__ void mma_tf32(float c[4], const uint32_t a[4],
                                         uint32_t b0, uint32_t b1) {
    asm volatile(
        "mma.sync.aligned.m16n8k8.row.col.f32.tf32.tf32.f32 "
        "{%0,%1,%2,%3}, {%4,%5,%6,%7}, {%8,%9}, {%0,%1,%2,%3};"
        : "+f"(c[0]), "+f"(c[1]), "+f"(c[2]), "+f"(c[3])
        : "r"(a[0]), "r"(a[1]), "r"(a[2]), "r"(a[3]), "r"(b0), "r"(b1));
}

// ---------------------------------------------------------------------------
// Kernel 1: hws = (h @ W) * norm[row]   -- tf32 tensor-core GEMM (unchanged R2)
// ---------------------------------------------------------------------------
constexpr int BM = 128;
constexpr int KC = 32;
constexpr int AS = 36;
constexpr int BS = 72;

__global__ __launch_bounds__(256) void gemm_tc_kernel(
    const float* __restrict__ h,
    const float* __restrict__ W,
    const float* __restrict__ norm)
{
    __shared__ uint32_t shA[BM * AS];
    __shared__ uint32_t shB[KC * BS];

    const int tid  = threadIdx.x;
    const int warp = tid >> 5;
    const int lane = tid & 31;
    const int block_row = blockIdx.x * BM;
    const int wr = warp * 16;
    const int grp = lane >> 2;
    const int tig = lane & 3;

    float acc[8][4] = {};

    for (int kc = 0; kc < IN_F; kc += KC) {
#pragma unroll
        for (int j = 0; j < 4; ++j) {
            const int linear = tid + 256 * j;
            const int row = linear >> 3;
            const int kk  = (linear & 7) * 4;
            const int grow = block_row + row;
            float4 v = make_float4(0.f, 0.f, 0.f, 0.f);
            if (grow < N_NODES)
                v = *reinterpret_cast<const float4*>(h + (size_t)grow * IN_F + kc + kk);
            uint32_t* p = &shA[row * AS + kk];
            p[0] = f2tf32(v.x); p[1] = f2tf32(v.y);
            p[2] = f2tf32(v.z); p[3] = f2tf32(v.w);
        }
#pragma unroll
        for (int j = 0; j < 2; ++j) {
            const int linear = tid + 256 * j;
            const int k  = linear >> 4;
            const int cc = (linear & 15) * 4;
            const float4 v = *reinterpret_cast<const float4*>(
                W + (size_t)(kc + k) * OUT_F + cc);
            uint32_t* p = &shB[k * BS + cc];
            p[0] = f2tf32(v.x); p[1] = f2tf32(v.y);
            p[2] = f2tf32(v.z); p[3] = f2tf32(v.w);
        }
        __syncthreads();

#pragma unroll
        for (int k8 = 0; k8 < 4; ++k8) {
            const int k0 = k8 * 8;
            uint32_t a[4];
            const int ar = wr + grp;
            const int ac = k0 + tig;
            a[0] = shA[ar * AS + ac];
            a[1] = shA[(ar + 8) * AS + ac];
            a[2] = shA[ar * AS + ac + 4];
            a[3] = shA[(ar + 8) * AS + ac + 4];
#pragma unroll
            for (int nt = 0; nt < 8; ++nt) {
                const int bk = k0 + tig;
                const int bn = nt * 8 + grp;
                mma_tf32(acc[nt], a, shB[bk * BS + bn], shB[(bk + 4) * BS + bn]);
            }
        }
        __syncthreads();
    }

    const int r0 = block_row + wr + grp;
    const int r1 = r0 + 8;
    const float s0 = (r0 < N_NODES) ? norm[r0] : 0.f;
    const float s1 = (r1 < N_NODES) ? norm[r1] : 0.f;
#pragma unroll
    for (int nt = 0; nt < 8; ++nt) {
        const int col = nt * 8 + tig * 2;
        if (r0 < N_NODES) {
            float2 v; v.x = acc[nt][0] * s0; v.y = acc[nt][1] * s0;
            *reinterpret_cast<float2*>(g_hws + (size_t)r0 * OUT_F + col) = v;
        }
        if (r1 < N_NODES) {
            float2 v; v.x = acc[nt][2] * s1; v.y = acc[nt][3] * s1;
            *reinterpret_cast<float2*>(g_hws + (size_t)r1 * OUT_F + col) = v;
        }
    }
}

// ---------------------------------------------------------------------------
// CSR build: zero -> hist -> scan(x3) -> fill
// ---------------------------------------------------------------------------
__global__ __launch_bounds__(256) void zero_deg_kernel() {
    const int i = blockIdx.x * 256 + threadIdx.x;
    if (i < N_NODES) g_deg[i] = 0;
}

__global__ __launch_bounds__(256) void hist_kernel(const int* __restrict__ dst) {
    const int e = blockIdx.x * 256 + threadIdx.x;
    if (e < N_EDGES) atomicAdd(&g_deg[__ldg(dst + e)], 1);
}

__device__ __forceinline__ int warp_incl_scan(int v, int lane) {
#pragma unroll
    for (int d = 1; d < 32; d <<= 1) {
        const int t = __shfl_up_sync(0xFFFFFFFFu, v, d);
        if (lane >= d) v += t;
    }
    return v;
}

// per-block exclusive scan of g_deg -> g_off (local), block total -> g_part
__global__ __launch_bounds__(256) void scan1_kernel() {
    const int t = threadIdx.x, b = blockIdx.x;
    const int i = b * 256 + t;
    const int v = (i < N_NODES) ? g_deg[i] : 0;
    const int lane = t & 31, w = t >> 5;
    const int incl = warp_incl_scan(v, lane);
    __shared__ int ws[8];
    if (lane == 31) ws[w] = incl;
    __syncthreads();
    if (t < 8) {
        int x = ws[t];
#pragma unroll
        for (int d = 1; d < 8; d <<= 1) {
            const int y = __shfl_up_sync(0xFFu, x, d);
            if (t >= d) x += y;
        }
        ws[t] = x;
    }
    __syncthreads();
    const int woff = w ? ws[w - 1] : 0;
    if (i < N_NODES) g_off[i] = woff + incl - v;
    if (t == 0) g_part[b] = ws[7];
}

// single-block exclusive scan of the 196 block partials (in place)
__global__ __launch_bounds__(256) void scan2_kernel() {
    const int t = threadIdx.x;
    const int v = (t < NB_NODES) ? g_part[t] : 0;
    const int lane = t & 31, w = t >> 5;
    const int incl = warp_incl_scan(v, lane);
    __shared__ int ws[8];
    if (lane == 31) ws[w] = incl;
    __syncthreads();
    if (t < 8) {
        int x = ws[t];
#pragma unroll
        for (int d = 1; d < 8; d <<= 1) {
            const int y = __shfl_up_sync(0xFFu, x, d);
            if (t >= d) x += y;
        }
        ws[t] = x;
    }
    __syncthreads();
    const int woff = w ? ws[w - 1] : 0;
    if (t < NB_NODES) g_part[t] = woff + incl - v;
}

// add block partials; init cursors
__global__ __launch_bounds__(256) void scan3_kernel() {
    const int i = blockIdx.x * 256 + threadIdx.x;
    if (i < N_NODES) {
        const int o = g_off[i] + g_part[i >> 8];
        g_off[i] = o;
        g_cursor[i] = o;
    }
}

__global__ __launch_bounds__(256) void fill_kernel(
    const int* __restrict__ src, const int* __restrict__ dst)
{
    const int e = blockIdx.x * 256 + threadIdx.x;
    if (e < N_EDGES) {
        const int d = __ldg(dst + e);
        const int pos = atomicAdd(&g_cursor[d], 1);
        g_esrc[pos] = __ldg(src + e);
    }
}

// ---------------------------------------------------------------------------
// Aggregate + fused epilogue:
//   out[n] = relu( (sum_{e in CSR[n]} hws[esrc[e]]) * norm[n] + bias )
// 16 threads per node, float4 per thread, 2 independent partial sums for MLP.
// ---------------------------------------------------------------------------
__global__ __launch_bounds__(256) void aggregate_kernel(
    const float* __restrict__ norm,
    const float* __restrict__ bias,
    float* __restrict__ out)
{
    const int g = blockIdx.x * 256 + threadIdx.x;   // exactly 800000 threads
    const int node = g >> 4;
    const int part = (g & 15) * 4;

    const int base = g_off[node];
    const int deg  = g_deg[node];

    float4 a0 = make_float4(0.f, 0.f, 0.f, 0.f);
    float4 a1 = make_float4(0.f, 0.f, 0.f, 0.f);

    int j = 0;
    for (; j + 1 < deg; j += 2) {
        const int s0 = __ldg(g_esrc + base + j);
        const int s1 = __ldg(g_esrc + base + j + 1);
        const float4 v0 = *reinterpret_cast<const float4*>(g_hws + (size_t)s0 * OUT_F + part);
        const float4 v1 = *reinterpret_cast<const float4*>(g_hws + (size_t)s1 * OUT_F + part);
        a0.x += v0.x; a0.y += v0.y; a0.z += v0.z; a0.w += v0.w;
        a1.x += v1.x; a1.y += v1.y; a1.z += v1.z; a1.w += v1.w;
    }
    if (j < deg) {
        const int s0 = __ldg(g_esrc + base + j);
        const float4 v0 = *reinterpret_cast<const float4*>(g_hws + (size_t)s0 * OUT_F + part);
        a0.x += v0.x; a0.y += v0.y; a0.z += v0.z; a0.w += v0.w;
    }

    const float sn = __ldg(norm + node);
    const float4 b = reinterpret_cast<const float4*>(bias)[g & 15];

    float4 o;
    o.x = fmaxf(fmaf(a0.x + a1.x, sn, b.x), 0.f);
    o.y = fmaxf(fmaf(a0.y + a1.y, sn, b.y), 0.f);
    o.z = fmaxf(fmaf(a0.z + a1.z, sn, b.z), 0.f);
    o.w = fmaxf(fmaf(a0.w + a1.w, sn, b.w), 0.f);
    *reinterpret_cast<float4*>(out + (size_t)node * OUT_F + part) = o;
}

// ---------------------------------------------------------------------------
// Launch
// Inputs: 0:h [50000,256] f32  1:norm [50000] f32  2:src [800000] i32
//         3:dst [800000] i32   4:weight [256,64] f32  5:bias [64] f32
// Output: [50000, 64] f32
// ---------------------------------------------------------------------------
extern "C" void kernel_launch(void* const* d_in, const int* in_sizes, int n_in,
                              void* d_out, int out_size)
{
    const float* h    = (const float*)d_in[0];
    const float* norm = (const float*)d_in[1];
    const int*   src  = (const int*)d_in[2];
    const int*   dst  = (const int*)d_in[3];
    const float* W    = (const float*)d_in[4];
    const float* bias = (const float*)d_in[5];
    float* out = (float*)d_out;

    const int EB = (N_EDGES + 255) / 256;  // 3125

    // 1) hws = (h @ W) * norm   (tf32 tensor cores)
    gemm_tc_kernel<<<(N_NODES + BM - 1) / BM, 256>>>(h, W, norm);

    // 2) CSR build on dst
    zero_deg_kernel<<<NB_NODES, 256>>>();
    hist_kernel<<<EB, 256>>>(dst);
    scan1_kernel<<<NB_NODES, 256>>>();
    scan2_kernel<<<1, 256>>>();
    scan3_kernel<<<NB_NODES, 256>>>();
    fill_kernel<<<EB, 256>>>(src, dst);

    // 3) out[n] = relu(sum(hws[esrc]) * norm[n] + bias)   (no atomics, no memset)
    aggregate_kernel<<<(N_NODES * 16) / 256, 256>>>(norm, bias, out);
}

// round 4
// speedup vs baseline: 1.4390x; 1.0048x over previous
#include <cuda_runtime.h>
#include <cuda_bf16.h>
#include <cstdint>

// Problem constants (fixed by the reference)
constexpr int N_NODES = 50000;
constexpr int N_EDGES = 800000;
constexpr int IN_F    = 256;
constexpr int OUT_F   = 64;

constexpr int NB_NODES = (N_NODES + 255) / 256;   // 196 scan blocks

// Scratch (device globals: no allocation allowed in kernel_launch)
__device__ float g_hws[(size_t)N_NODES * OUT_F];  // (h@W)*norm  : 12.8 MB, L2-resident
__device__ int   g_esrc[N_EDGES];                 // src ids grouped by dst bucket
__device__ int   g_deg[N_NODES];                  // in-degree per node
__device__ int   g_off[N_NODES];                  // CSR offsets (exclusive scan of deg)
__device__ int   g_cursor[N_NODES];               // fill cursors
__device__ int   g_part[256];                     // scan block partials

// ---------------------------------------------------------------------------
// tf32 helpers
// ---------------------------------------------------------------------------
__device__ __forceinline__ uint32_t f2tf32(float x) {
    uint32_t r;
    asm("cvt.rna.tf32.f32 %0, %1;" : "=r"(r) : "f"(x));
    return r;
}

__device__ __forceinline__ void mma_tf32(float c[4], const uint32_t a[4],
                                         uint32_t b0, uint32_t b1) {
    asm volatile(
        "mma.sync.aligned.m16n8k8.row.col.f32.tf32.tf32.f32 "
        "{%0,%1,%2,%3}, {%4,%5,%6,%7}, {%8,%9}, {%0,%1,%2,%3};"
        : "+f"(c[0]), "+f"(c[1]), "+f"(c[2]), "+f"(c[3])
        : "r"(a[0]), "r"(a[1]), "r"(a[2]), "r"(a[3]), "r"(b0), "r"(b1));
}

// ---------------------------------------------------------------------------
// Kernel 1: hws = (h @ W) * norm[row]   -- tf32 tensor-core GEMM (unchanged R2)
// ---------------------------------------------------------------------------
constexpr int BM = 128;
constexpr int KC = 32;
constexpr int AS = 36;
constexpr int BS = 72;

__global__ __launch_bounds__(256) void gemm_tc_kernel(
    const float* __restrict__ h,
    const float* __restrict__ W,
    const float* __restrict__ norm)
{
    __shared__ uint32_t shA[BM * AS];
    __shared__ uint32_t shB[KC * BS];

    const int tid  = threadIdx.x;
    const int warp = tid >> 5;
    const int lane = tid & 31;
    const int block_row = blockIdx.x * BM;
    const int wr = warp * 16;
    const int grp = lane >> 2;
    const int tig = lane & 3;

    float acc[8][4] = {};

    for (int kc = 0; kc < IN_F; kc += KC) {
#pragma unroll
        for (int j = 0; j < 4; ++j) {
            const int linear = tid + 256 * j;
            const int row = linear >> 3;
            const int kk  = (linear & 7) * 4;
            const int grow = block_row + row;
            float4 v = make_float4(0.f, 0.f, 0.f, 0.f);
            if (grow < N_NODES)
                v = *reinterpret_cast<const float4*>(h + (size_t)grow * IN_F + kc + kk);
            uint32_t* p = &shA[row * AS + kk];
            p[0] = f2tf32(v.x); p[1] = f2tf32(v.y);
            p[2] = f2tf32(v.z); p[3] = f2tf32(v.w);
        }
#pragma unroll
        for (int j = 0; j < 2; ++j) {
            const int linear = tid + 256 * j;
            const int k  = linear >> 4;
            const int cc = (linear & 15) * 4;
            const float4 v = *reinterpret_cast<const float4*>(
                W + (size_t)(kc + k) * OUT_F + cc);
            uint32_t* p = &shB[k * BS + cc];
            p[0] = f2tf32(v.x); p[1] = f2tf32(v.y);
            p[2] = f2tf32(v.z); p[3] = f2tf32(v.w);
        }
        __syncthreads();

#pragma unroll
        for (int k8 = 0; k8 < 4; ++k8) {
            const int k0 = k8 * 8;
            uint32_t a[4];
            const int ar = wr + grp;
            const int ac = k0 + tig;
            a[0] = shA[ar * AS + ac];
            a[1] = shA[(ar + 8) * AS + ac];
            a[2] = shA[ar * AS + ac + 4];
            a[3] = shA[(ar + 8) * AS + ac + 4];
#pragma unroll
            for (int nt = 0; nt < 8; ++nt) {
                const int bk = k0 + tig;
                const int bn = nt * 8 + grp;
                mma_tf32(acc[nt], a, shB[bk * BS + bn], shB[(bk + 4) * BS + bn]);
            }
        }
        __syncthreads();
    }

    const int r0 = block_row + wr + grp;
    const int r1 = r0 + 8;
    const float s0 = (r0 < N_NODES) ? norm[r0] : 0.f;
    const float s1 = (r1 < N_NODES) ? norm[r1] : 0.f;
#pragma unroll
    for (int nt = 0; nt < 8; ++nt) {
        const int col = nt * 8 + tig * 2;
        if (r0 < N_NODES) {
            float2 v; v.x = acc[nt][0] * s0; v.y = acc[nt][1] * s0;
            *reinterpret_cast<float2*>(g_hws + (size_t)r0 * OUT_F + col) = v;
        }
        if (r1 < N_NODES) {
            float2 v; v.x = acc[nt][2] * s1; v.y = acc[nt][3] * s1;
            *reinterpret_cast<float2*>(g_hws + (size_t)r1 * OUT_F + col) = v;
        }
    }
}

// ---------------------------------------------------------------------------
// CSR build: zero -> hist -> scan(x3) -> fill
// ---------------------------------------------------------------------------
__global__ __launch_bounds__(256) void zero_deg_kernel() {
    const int i = blockIdx.x * 256 + threadIdx.x;
    if (i < N_NODES) g_deg[i] = 0;
}

__global__ __launch_bounds__(256) void hist_kernel(const int* __restrict__ dst) {
    const int e = blockIdx.x * 256 + threadIdx.x;
    if (e < N_EDGES) atomicAdd(&g_deg[__ldg(dst + e)], 1);
}

__device__ __forceinline__ int warp_incl_scan(int v, int lane) {
#pragma unroll
    for (int d = 1; d < 32; d <<= 1) {
        const int t = __shfl_up_sync(0xFFFFFFFFu, v, d);
        if (lane >= d) v += t;
    }
    return v;
}

// per-block exclusive scan of g_deg -> g_off (local), block total -> g_part
__global__ __launch_bounds__(256) void scan1_kernel() {
    const int t = threadIdx.x, b = blockIdx.x;
    const int i = b * 256 + t;
    const int v = (i < N_NODES) ? g_deg[i] : 0;
    const int lane = t & 31, w = t >> 5;
    const int incl = warp_incl_scan(v, lane);
    __shared__ int ws[8];
    if (lane == 31) ws[w] = incl;
    __syncthreads();
    if (t < 8) {
        int x = ws[t];
#pragma unroll
        for (int d = 1; d < 8; d <<= 1) {
            const int y = __shfl_up_sync(0xFFu, x, d);
            if (t >= d) x += y;
        }
        ws[t] = x;
    }
    __syncthreads();
    const int woff = w ? ws[w - 1] : 0;
    if (i < N_NODES) g_off[i] = woff + incl - v;
    if (t == 0) g_part[b] = ws[7];
}

// single-block exclusive scan of the 196 block partials (in place)
__global__ __launch_bounds__(256) void scan2_kernel() {
    const int t = threadIdx.x;
    const int v = (t < NB_NODES) ? g_part[t] : 0;
    const int lane = t & 31, w = t >> 5;
    const int incl = warp_incl_scan(v, lane);
    __shared__ int ws[8];
    if (lane == 31) ws[w] = incl;
    __syncthreads();
    if (t < 8) {
        int x = ws[t];
#pragma unroll
        for (int d = 1; d < 8; d <<= 1) {
            const int y = __shfl_up_sync(0xFFu, x, d);
            if (t >= d) x += y;
        }
        ws[t] = x;
    }
    __syncthreads();
    const int woff = w ? ws[w - 1] : 0;
    if (t < NB_NODES) g_part[t] = woff + incl - v;
}

// add block partials; init cursors
__global__ __launch_bounds__(256) void scan3_kernel() {
    const int i = blockIdx.x * 256 + threadIdx.x;
    if (i < N_NODES) {
        const int o = g_off[i] + g_part[i >> 8];
        g_off[i] = o;
        g_cursor[i] = o;
    }
}

__global__ __launch_bounds__(256) void fill_kernel(
    const int* __restrict__ src, const int* __restrict__ dst)
{
    const int e = blockIdx.x * 256 + threadIdx.x;
    if (e < N_EDGES) {
        const int d = __ldg(dst + e);
        const int pos = atomicAdd(&g_cursor[d], 1);
        g_esrc[pos] = __ldg(src + e);
    }
}

// ---------------------------------------------------------------------------
// Aggregate + fused epilogue:
//   out[n] = relu( (sum_{e in CSR[n]} hws[esrc[e]]) * norm[n] + bias )
// 16 threads per node, float4 per thread, 2 independent partial sums for MLP.
// ---------------------------------------------------------------------------
__global__ __launch_bounds__(256) void aggregate_kernel(
    const float* __restrict__ norm,
    const float* __restrict__ bias,
    float* __restrict__ out)
{
    const int g = blockIdx.x * 256 + threadIdx.x;   // exactly 800000 threads
    const int node = g >> 4;
    const int part = (g & 15) * 4;

    const int base = g_off[node];
    const int deg  = g_deg[node];

    float4 a0 = make_float4(0.f, 0.f, 0.f, 0.f);
    float4 a1 = make_float4(0.f, 0.f, 0.f, 0.f);

    int j = 0;
    for (; j + 1 < deg; j += 2) {
        const int s0 = __ldg(g_esrc + base + j);
        const int s1 = __ldg(g_esrc + base + j + 1);
        const float4 v0 = *reinterpret_cast<const float4*>(g_hws + (size_t)s0 * OUT_F + part);
        const float4 v1 = *reinterpret_cast<const float4*>(g_hws + (size_t)s1 * OUT_F + part);
        a0.x += v0.x; a0.y += v0.y; a0.z += v0.z; a0.w += v0.w;
        a1.x += v1.x; a1.y += v1.y; a1.z += v1.z; a1.w += v1.w;
    }
    if (j < deg) {
        const int s0 = __ldg(g_esrc + base + j);
        const float4 v0 = *reinterpret_cast<const float4*>(g_hws + (size_t)s0 * OUT_F + part);
        a0.x += v0.x; a0.y += v0.y; a0.z += v0.z; a0.w += v0.w;
    }

    const float sn = __ldg(norm + node);
    const float4 b = reinterpret_cast<const float4*>(bias)[g & 15];

    float4 o;
    o.x = fmaxf(fmaf(a0.x + a1.x, sn, b.x), 0.f);
    o.y = fmaxf(fmaf(a0.y + a1.y, sn, b.y), 0.f);
    o.z = fmaxf(fmaf(a0.z + a1.z, sn, b.z), 0.f);
    o.w = fmaxf(fmaf(a0.w + a1.w, sn, b.w), 0.f);
    *reinterpret_cast<float4*>(out + (size_t)node * OUT_F + part) = o;
}

// ---------------------------------------------------------------------------
// Launch
// Inputs: 0:h [50000,256] f32  1:norm [50000] f32  2:src [800000] i32
//         3:dst [800000] i32   4:weight [256,64] f32  5:bias [64] f32
// Output: [50000, 64] f32
// ---------------------------------------------------------------------------
extern "C" void kernel_launch(void* const* d_in, const int* in_sizes, int n_in,
                              void* d_out, int out_size)
{
    const float* h    = (const float*)d_in[0];
    const float* norm = (const float*)d_in[1];
    const int*   src  = (const int*)d_in[2];
    const int*   dst  = (const int*)d_in[3];
    const float* W    = (const float*)d_in[4];
    const float* bias = (const float*)d_in[5];
    float* out = (float*)d_out;

    const int EB = (N_EDGES + 255) / 256;  // 3125

    // 1) hws = (h @ W) * norm   (tf32 tensor cores)
    gemm_tc_kernel<<<(N_NODES + BM - 1) / BM, 256>>>(h, W, norm);

    // 2) CSR build on dst
    zero_deg_kernel<<<NB_NODES, 256>>>();
    hist_kernel<<<EB, 256>>>(dst);
    scan1_kernel<<<NB_NODES, 256>>>();
    scan2_kernel<<<1, 256>>>();
    scan3_kernel<<<NB_NODES, 256>>>();
    fill_kernel<<<EB, 256>>>(src, dst);

    // 3) out[n] = relu(sum(hws[esrc]) * norm[n] + bias)   (no atomics, no memset)
    aggregate_kernel<<<(N_NODES * 16) / 256, 256>>>(norm, bias, out);
}